// round 3
// baseline (speedup 1.0000x reference)
#include <cuda_runtime.h>
#include <math.h>

#define NBATCH 16
#define NP     4096
#define TOTAL  (NBATCH * NP)      // 65536 points per tensor
#define NB     256                // x-bins per batch
#define LOV    (-5.0f)
#define HIV    (5.0f)
#define WBIN   ((HIV - LOV) / NB)
#define INVW   ((float)NB / (HIV - LOV))
#define CTHREADS 256
#define CBLOCKS  512              // 2 dirs * 16 batches * 16 query tiles

// Scratch (no allocation allowed).
// g_sorted: per (tensor,batch), points bucketed by x-bin, as {x,y,z, 0.5*|p|^2}.
// g_binstart[row][k] = start offset of bin k within that batch (row = t*16+b, t: 0=x,1=y).
__device__ float4 g_sorted[2 * TOTAL];
__device__ int    g_binstart[32][NB + 1];
__device__ float  g_partial[CBLOCKS];

__device__ __forceinline__ int binof(float v) {
    int b = (int)((v - LOV) * INVW);
    return min(max(b, 0), NB - 1);
}

// One block per (tensor, batch): count -> prefix -> scatter.
__global__ __launch_bounds__(256) void bucket_kernel(const float* __restrict__ x,
                                                     const float* __restrict__ y) {
    int blk = blockIdx.x;             // 0..31
    int t = blk >> 4, b = blk & 15;
    const float* src = (t ? y : x) + (size_t)b * NP * 3;

    __shared__ int cnt[NB];
    __shared__ int base[NB + 1];
    int tid = threadIdx.x;

    cnt[tid] = 0;                     // 256 threads == NB
    __syncthreads();
    for (int i = tid; i < NP; i += 256)
        atomicAdd(&cnt[binof(src[3 * i])], 1);
    __syncthreads();
    if (tid == 0) {
        int s = 0;
        for (int k = 0; k < NB; k++) { base[k] = s; s += cnt[k]; }
        base[NB] = s;
    }
    __syncthreads();
    g_binstart[blk][tid] = base[tid];
    if (tid == 0) g_binstart[blk][NB] = base[NB];
    cnt[tid] = 0;
    __syncthreads();

    float4* dst = g_sorted + (size_t)t * TOTAL + (size_t)b * NP;
    for (int i = tid; i < NP; i += 256) {
        float a = src[3 * i + 0];
        float c = src[3 * i + 1];
        float d = src[3 * i + 2];
        int bin = binof(a);
        int pos = base[bin] + atomicAdd(&cnt[bin], 1);
        dst[pos] = make_float4(a, c, d, 0.5f * (a * a + c * c + d * d));
    }
}

__global__ __launch_bounds__(CTHREADS) void chamfer_kernel() {
    __shared__ int   sbs[NB + 1];
    __shared__ float red[CTHREADS];

    int blk = blockIdx.x;
    int dir = blk >> 8;               // 0: queries=x, db=y ; 1: swapped
    int b   = (blk >> 4) & 15;
    int qt  = blk & 15;
    int tid = threadIdx.x;

    const float4* qArr = g_sorted + (dir ? TOTAL : 0) + (size_t)b * NP;
    const float4* db   = g_sorted + (dir ? 0 : TOTAL) + (size_t)b * NP;
    const int*    bs   = g_binstart[(dir ? 0 : 16) + b];

    for (int k = tid; k <= NB; k += CTHREADS) sbs[k] = bs[k];
    __syncthreads();

    float4 q  = qArr[qt * CTHREADS + tid];
    float  qw = q.w;

    unsigned myBin = (unsigned)binof(q.x);
    unsigned bL = __reduce_min_sync(0xFFFFFFFFu, myBin);
    unsigned bR = __reduce_max_sync(0xFFFFFFFFu, myBin);

    float m0 = 1e30f, m1 = 1e30f;

    // Evaluate db[j] for j in [s,e): t_j = 0.5|s_j|^2 - q.s_j (min over j).
    auto evalRange = [&](int s, int e) {
        int j = s;
        for (; j + 2 <= e; j += 2) {
            float4 p0 = __ldg(&db[j]);
            float4 p1 = __ldg(&db[j + 1]);
            float t0 = fmaf(-q.x, p0.x, fmaf(-q.y, p0.y, fmaf(-q.z, p0.z, p0.w)));
            float t1 = fmaf(-q.x, p1.x, fmaf(-q.y, p1.y, fmaf(-q.z, p1.z, p1.w)));
            m0 = fminf(m0, t0);
            m1 = fminf(m1, t1);
        }
        if (j < e) {
            float4 p0 = __ldg(&db[j]);
            float t0 = fmaf(-q.x, p0.x, fmaf(-q.y, p0.y, fmaf(-q.z, p0.z, p0.w)));
            m0 = fminf(m0, t0);
        }
    };

    // Initial window: the warp's own query bins.
    evalRange(sbs[bL], sbs[bR + 1]);

    // Expand until the axis-gap bound proves the min for every lane.
    // sq_best = 2*(qw + tmin); exclude side when 0.5*gap^2 >= qw + tmin.
    while (true) {
        float tmin  = fminf(m0, m1);
        float edgeL = LOV + (float)bL * WBIN;
        float edgeR = LOV + (float)(bR + 1) * WBIN;
        float gl = fmaxf(q.x - edgeL, 0.0f);
        float gr = fmaxf(edgeR - q.x, 0.0f);
        bool dL = (bL == 0)      || __all_sync(0xFFFFFFFFu, 0.5f * gl * gl >= qw + tmin);
        bool dR = (bR == NB - 1) || __all_sync(0xFFFFFFFFu, 0.5f * gr * gr >= qw + tmin);
        if (dL && dR) break;
        if (!dL) { bL--; evalRange(sbs[bL], sbs[bL + 1]); }
        if (!dR) { bR++; evalRange(sbs[bR], sbs[bR + 1]); }
    }

    float m = fminf(m0, m1);
    float d = sqrtf(1e-6f + fmaxf(2.0f * (qw + m), 0.0f));

    // Deterministic fixed-tree block reduction.
    red[tid] = d;
    __syncthreads();
    #pragma unroll
    for (int s = CTHREADS / 2; s > 0; s >>= 1) {
        if (tid < s) red[tid] += red[tid + s];
        __syncthreads();
    }
    if (tid == 0) g_partial[blk] = red[0];
}

__global__ void finalize_kernel(float* __restrict__ out) {
    __shared__ float red[CBLOCKS];
    int tid = threadIdx.x;
    red[tid] = g_partial[tid];
    __syncthreads();
    #pragma unroll
    for (int s = CBLOCKS / 2; s > 0; s >>= 1) {
        if (tid < s) red[tid] += red[tid + s];
        __syncthreads();
    }
    if (tid == 0) out[0] = red[0] * (1.0f / (float)TOTAL);
}

extern "C" void kernel_launch(void* const* d_in, const int* in_sizes, int n_in,
                              void* d_out, int out_size) {
    const float* x = (const float*)d_in[0];
    const float* y = (const float*)d_in[1];
    float* out = (float*)d_out;

    bucket_kernel<<<32, 256>>>(x, y);
    chamfer_kernel<<<CBLOCKS, CTHREADS>>>();
    finalize_kernel<<<1, CBLOCKS>>>(out);
}

// round 4
// speedup vs baseline: 1.0985x; 1.0985x over previous
#include <cuda_runtime.h>
#include <math.h>

#define NBATCH 16
#define NP     4096
#define TOTAL  (NBATCH * NP)      // 65536 points per tensor
#define ROWS   32                 // (tensor, batch) rows: 0-15 = x, 16-31 = y
#define NB     256                // x-bins per batch
#define LOV    (-5.0f)
#define HIV    (5.0f)
#define WBIN   ((HIV - LOV) / NB)
#define INVW   ((float)NB / (HIV - LOV))
#define WINIT  544                // target initial window size (points)
#define CTHREADS 256
#define CBLOCKS  512              // 2 dirs * 16 batches * 16 query tiles

// Scratch (no allocation allowed).
__device__ float4 g_sorted[2 * TOTAL];   // bucketed {x,y,z, 0.5|p|^2} per row
__device__ int    g_hist[ROWS][NB];
__device__ int    g_cursor[ROWS][NB];
__device__ int    g_binstart[ROWS][NB + 1];
__device__ float  g_partial[CBLOCKS];

__device__ __forceinline__ int binof(float v) {
    int b = (int)((v - LOV) * INVW);
    return min(max(b, 0), NB - 1);
}

__global__ void zero_kernel() {
    g_hist[blockIdx.x][threadIdx.x] = 0;
    g_cursor[blockIdx.x][threadIdx.x] = 0;
}

// 256 blocks: 8 blocks per row, 512 points per block.
__global__ __launch_bounds__(256) void hist_kernel(const float* __restrict__ x,
                                                   const float* __restrict__ y) {
    int row = blockIdx.x >> 3, seg = blockIdx.x & 7;
    const float* src = ((row >= 16) ? y : x) + (size_t)(row & 15) * NP * 3;
    __shared__ int h[NB];
    int tid = threadIdx.x;
    h[tid] = 0;
    __syncthreads();
    int p0 = seg * 512 + tid * 2;
    atomicAdd(&h[binof(src[3 * p0])], 1);
    atomicAdd(&h[binof(src[3 * (p0 + 1)])], 1);
    __syncthreads();
    if (h[tid]) atomicAdd(&g_hist[row][tid], h[tid]);
}

// One block per row: Hillis-Steele inclusive scan -> exclusive starts.
__global__ __launch_bounds__(NB) void prefix_kernel() {
    int row = blockIdx.x, tid = threadIdx.x;
    __shared__ int s[NB];
    int v = g_hist[row][tid];
    s[tid] = v;
    __syncthreads();
    #pragma unroll
    for (int off = 1; off < NB; off <<= 1) {
        int t = (tid >= off) ? s[tid - off] : 0;
        __syncthreads();
        s[tid] += t;
        __syncthreads();
    }
    g_binstart[row][tid] = s[tid] - v;      // exclusive
    if (tid == NB - 1) g_binstart[row][NB] = s[tid];
}

// 256 blocks, 2 consecutive points per thread (vectorized 3x float2 read).
__global__ __launch_bounds__(256) void scatter_kernel(const float* __restrict__ x,
                                                      const float* __restrict__ y) {
    int row = blockIdx.x >> 3, seg = blockIdx.x & 7;
    const float* src = ((row >= 16) ? y : x) + (size_t)(row & 15) * NP * 3;
    int p0 = seg * 512 + threadIdx.x * 2;

    const float2* s2 = (const float2*)(src + 3 * p0);
    float2 ab = s2[0], ca = s2[1], bc = s2[2];

    float4* dst = g_sorted + (size_t)row * NP;

    {
        int bin = binof(ab.x);
        int pos = g_binstart[row][bin] + atomicAdd(&g_cursor[row][bin], 1);
        dst[pos] = make_float4(ab.x, ab.y, ca.x,
                               0.5f * (ab.x * ab.x + ab.y * ab.y + ca.x * ca.x));
    }
    {
        int bin = binof(ca.y);
        int pos = g_binstart[row][bin] + atomicAdd(&g_cursor[row][bin], 1);
        dst[pos] = make_float4(ca.y, bc.x, bc.y,
                               0.5f * (ca.y * ca.y + bc.x * bc.x + bc.y * bc.y));
    }
}

__global__ __launch_bounds__(CTHREADS) void chamfer_kernel() {
    __shared__ int   sbs[NB + 1];
    __shared__ float red[CTHREADS];

    int blk = blockIdx.x;
    int dir = blk >> 8;               // 0: queries=x, db=y ; 1: swapped
    int b   = (blk >> 4) & 15;
    int qt  = blk & 15;
    int tid = threadIdx.x;

    int qRow  = dir ? (16 + b) : b;
    int dbRow = dir ? b : (16 + b);
    const float4* qArr = g_sorted + (size_t)qRow * NP;
    const float4* db   = g_sorted + (size_t)dbRow * NP;
    const int*    bs   = g_binstart[dbRow];

    for (int k = tid; k <= NB; k += CTHREADS) sbs[k] = bs[k];
    __syncthreads();

    float4 q  = qArr[qt * CTHREADS + tid];
    float  qw = q.w;

    float m0 = 1e30f, m1 = 1e30f, m2 = 1e30f, m3 = 1e30f;

    // min over j in [s,e) of t_j = 0.5|s_j|^2 - q.s_j   (broadcast loads, MLP 8)
    auto evalRange = [&](int s, int e) {
        int j = s;
        #pragma unroll 2
        for (; j + 4 <= e; j += 4) {
            float4 p0 = __ldg(&db[j]);
            float4 p1 = __ldg(&db[j + 1]);
            float4 p2 = __ldg(&db[j + 2]);
            float4 p3 = __ldg(&db[j + 3]);
            m0 = fminf(m0, fmaf(-q.x, p0.x, fmaf(-q.y, p0.y, fmaf(-q.z, p0.z, p0.w))));
            m1 = fminf(m1, fmaf(-q.x, p1.x, fmaf(-q.y, p1.y, fmaf(-q.z, p1.z, p1.w))));
            m2 = fminf(m2, fmaf(-q.x, p2.x, fmaf(-q.y, p2.y, fmaf(-q.z, p2.z, p2.w))));
            m3 = fminf(m3, fmaf(-q.x, p3.x, fmaf(-q.y, p3.y, fmaf(-q.z, p3.z, p3.w))));
        }
        for (; j < e; ++j) {
            float4 p0 = __ldg(&db[j]);
            m0 = fminf(m0, fmaf(-q.x, p0.x, fmaf(-q.y, p0.y, fmaf(-q.z, p0.z, p0.w))));
        }
    };

    // Warp-uniform window: span of lanes' bins, extended to >= WINIT points.
    unsigned myBin = (unsigned)binof(q.x);
    int kL = (int)__reduce_min_sync(0xFFFFFFFFu, myBin);
    int kR = (int)__reduce_max_sync(0xFFFFFFFFu, myBin);
    while (sbs[kR + 1] - sbs[kL] < WINIT && (kL > 0 || kR < NB - 1)) {
        if (kL > 0) kL--;
        if (kR < NB - 1) kR++;
    }

    // One big contiguous evaluation (the hot path).
    evalRange(sbs[kL], sbs[kR + 1]);

    // Exact exclusion bound; expand per-bin only if needed (rare).
    while (true) {
        float tmin  = fminf(fminf(m0, m1), fminf(m2, m3));
        float edgeL = LOV + (float)kL * WBIN;
        float edgeR = LOV + (float)(kR + 1) * WBIN;
        float gl = fmaxf(q.x - edgeL, 0.0f);
        float gr = fmaxf(edgeR - q.x, 0.0f);
        bool dL = (kL == 0)      || __all_sync(0xFFFFFFFFu, 0.5f * gl * gl >= qw + tmin);
        bool dR = (kR == NB - 1) || __all_sync(0xFFFFFFFFu, 0.5f * gr * gr >= qw + tmin);
        if (dL && dR) break;
        if (!dL) { kL--; evalRange(sbs[kL], sbs[kL + 1]); }
        if (!dR) { kR++; evalRange(sbs[kR], sbs[kR + 1]); }
    }

    float m = fminf(fminf(m0, m1), fminf(m2, m3));
    float d = sqrtf(1e-6f + fmaxf(2.0f * (qw + m), 0.0f));

    // Deterministic fixed-tree block reduction.
    red[tid] = d;
    __syncthreads();
    #pragma unroll
    for (int s = CTHREADS / 2; s > 0; s >>= 1) {
        if (tid < s) red[tid] += red[tid + s];
        __syncthreads();
    }
    if (tid == 0) g_partial[blk] = red[0];
}

__global__ void finalize_kernel(float* __restrict__ out) {
    __shared__ float red[CBLOCKS];
    int tid = threadIdx.x;
    red[tid] = g_partial[tid];
    __syncthreads();
    #pragma unroll
    for (int s = CBLOCKS / 2; s > 0; s >>= 1) {
        if (tid < s) red[tid] += red[tid + s];
        __syncthreads();
    }
    if (tid == 0) out[0] = red[0] * (1.0f / (float)TOTAL);
}

extern "C" void kernel_launch(void* const* d_in, const int* in_sizes, int n_in,
                              void* d_out, int out_size) {
    const float* x = (const float*)d_in[0];
    const float* y = (const float*)d_in[1];
    float* out = (float*)d_out;

    zero_kernel<<<ROWS, NB>>>();
    hist_kernel<<<256, 256>>>(x, y);
    prefix_kernel<<<ROWS, NB>>>();
    scatter_kernel<<<256, 256>>>(x, y);
    chamfer_kernel<<<CBLOCKS, CTHREADS>>>();
    finalize_kernel<<<1, CBLOCKS>>>(out);
}

// round 5
// speedup vs baseline: 2.8626x; 2.6060x over previous
#include <cuda_runtime.h>
#include <math.h>

#define NP     4096
#define TOTAL  65536              // points per tensor (16*4096)
#define ROWS   32                 // rows: 0-15 = x batches, 16-31 = y batches
#define NB     256
#define LOV    (-5.0f)
#define HIV    (5.0f)
#define WBIN   ((HIV - LOV) / NB)
#define INVW   ((float)NB / (HIV - LOV))
#define PADB   3                  // pad bins each side of block query span
#define WMIN   640                // min staged window points
#define WCAP   2048               // smem cap (32 KB)
#define FULLM  0xFFFFFFFFu

__device__ float4 g_sorted[2 * TOTAL];     // bucketed {x,y,z,0.5|p|^2} per row
__device__ int    g_hist[ROWS][NB];
__device__ int    g_cursor[ROWS][NB];
__device__ int    g_binstart[ROWS][NB + 1];
__device__ float  g_dist[2 * TOTAL];
__device__ int2   g_todo[2 * TOTAL];       // {qslot, min_bits}
__device__ int    g_nq;
__device__ float  g_partA[128];

__device__ __forceinline__ int binof(float v) {
    int b = (int)((v - LOV) * INVW);
    return min(max(b, 0), NB - 1);
}

__global__ void zero_kernel() {
    g_hist[blockIdx.x][threadIdx.x] = 0;
    g_cursor[blockIdx.x][threadIdx.x] = 0;
    if (blockIdx.x == 0 && threadIdx.x == 0) g_nq = 0;
}

// 256 blocks: 8 per row, 512 points each.
__global__ __launch_bounds__(256) void hist_kernel(const float* __restrict__ x,
                                                   const float* __restrict__ y) {
    int row = blockIdx.x >> 3, seg = blockIdx.x & 7;
    const float* src = ((row >= 16) ? y : x) + (size_t)(row & 15) * NP * 3;
    __shared__ int h[NB];
    int tid = threadIdx.x;
    h[tid] = 0;
    __syncthreads();
    int p0 = seg * 512 + tid * 2;
    atomicAdd(&h[binof(src[3 * p0])], 1);
    atomicAdd(&h[binof(src[3 * (p0 + 1)])], 1);
    __syncthreads();
    if (h[tid]) atomicAdd(&g_hist[row][tid], h[tid]);
}

__global__ __launch_bounds__(NB) void prefix_kernel() {
    int row = blockIdx.x, tid = threadIdx.x;
    __shared__ int s[NB];
    int v = g_hist[row][tid];
    s[tid] = v;
    __syncthreads();
    #pragma unroll
    for (int off = 1; off < NB; off <<= 1) {
        int t = (tid >= off) ? s[tid - off] : 0;
        __syncthreads();
        s[tid] += t;
        __syncthreads();
    }
    g_binstart[row][tid] = s[tid] - v;
    if (tid == NB - 1) g_binstart[row][NB] = s[tid];
}

__global__ __launch_bounds__(256) void scatter_kernel(const float* __restrict__ x,
                                                      const float* __restrict__ y) {
    int row = blockIdx.x >> 3, seg = blockIdx.x & 7;
    const float* src = ((row >= 16) ? y : x) + (size_t)(row & 15) * NP * 3;
    int p0 = seg * 512 + threadIdx.x * 2;
    const float2* s2 = (const float2*)(src + 3 * p0);
    float2 ab = s2[0], ca = s2[1], bc = s2[2];
    float4* dst = g_sorted + (size_t)row * NP;
    {
        int bin = binof(ab.x);
        int pos = g_binstart[row][bin] + atomicAdd(&g_cursor[row][bin], 1);
        dst[pos] = make_float4(ab.x, ab.y, ca.x,
                               0.5f * (ab.x * ab.x + ab.y * ab.y + ca.x * ca.x));
    }
    {
        int bin = binof(ca.y);
        int pos = g_binstart[row][bin] + atomicAdd(&g_cursor[row][bin], 1);
        dst[pos] = make_float4(ca.y, bc.x, bc.y,
                               0.5f * (ca.y * ca.y + bc.x * bc.x + bc.y * bc.y));
    }
}

// Phase 1: block-uniform staged window, per-lane exact bound check, spill rest.
__global__ __launch_bounds__(256) void phase1_kernel() {
    __shared__ int    sbs[NB + 1];
    __shared__ float4 swin[WCAP];
    __shared__ int    swlo, swcnt, skL, skR;

    int blk = blockIdx.x;                 // 512 blocks
    int dir = blk >> 8;
    int b   = (blk >> 4) & 15;
    int qt  = blk & 15;
    int tid = threadIdx.x;
    int qRow  = dir ? (16 + b) : b;
    int dbRow = dir ? b : (16 + b);
    const float4* qArr = g_sorted + (size_t)qRow * NP;
    const float4* db   = g_sorted + (size_t)dbRow * NP;

    for (int k = tid; k <= NB; k += 256) sbs[k] = g_binstart[dbRow][k];
    float4 q = qArr[qt * 256 + tid];
    int myBin = binof(q.x);
    if (tid == 0)   skL = myBin;          // queries sorted by bin -> tid0 = min
    if (tid == 255) skR = myBin;          // tid255 = max
    __syncthreads();

    if (tid == 0) {
        int kL = max(skL - PADB, 0);
        int kR = min(skR + PADB, NB - 1);
        while (sbs[kR + 1] - sbs[kL] < WMIN && (kL > 0 || kR < NB - 1)) {
            if (kL > 0) kL--;
            if (kR < NB - 1) kR++;
        }
        while (sbs[kR + 1] - sbs[kL] > WCAP) {   // essentially never
            if (kR > skR) kR--;
            else if (kL < skL) kL++;
            else break;
        }
        skL = kL; skR = kR;
        swlo  = sbs[kL];
        swcnt = min(sbs[kR + 1] - sbs[kL], WCAP);
    }
    __syncthreads();
    int lo = swlo, cnt = swcnt, kL = skL, kR = skR;
    for (int j = tid; j < cnt; j += 256) swin[j] = db[lo + j];
    __syncthreads();

    float m0 = 1e30f, m1 = 1e30f, m2 = 1e30f, m3 = 1e30f;
    int j = 0;
    #pragma unroll 2
    for (; j + 4 <= cnt; j += 4) {
        float4 p0 = swin[j], p1 = swin[j + 1], p2 = swin[j + 2], p3 = swin[j + 3];
        m0 = fminf(m0, fmaf(-q.x, p0.x, fmaf(-q.y, p0.y, fmaf(-q.z, p0.z, p0.w))));
        m1 = fminf(m1, fmaf(-q.x, p1.x, fmaf(-q.y, p1.y, fmaf(-q.z, p1.z, p1.w))));
        m2 = fminf(m2, fmaf(-q.x, p2.x, fmaf(-q.y, p2.y, fmaf(-q.z, p2.z, p2.w))));
        m3 = fminf(m3, fmaf(-q.x, p3.x, fmaf(-q.y, p3.y, fmaf(-q.z, p3.z, p3.w))));
    }
    for (; j < cnt; ++j) {
        float4 p0 = swin[j];
        m0 = fminf(m0, fmaf(-q.x, p0.x, fmaf(-q.y, p0.y, fmaf(-q.z, p0.z, p0.w))));
    }
    float m = fminf(fminf(m0, m1), fminf(m2, m3));

    // Exact per-lane exclusion bound at bin-edge window boundaries.
    float thr   = q.w + m;                                  // 0.5 * d^2
    float edgeL = LOV + (float)kL * WBIN;
    float edgeR = LOV + (float)(kR + 1) * WBIN;
    float gl = fmaxf(q.x - edgeL, 0.0f);
    float gr = fmaxf(edgeR - q.x, 0.0f);
    bool doneL = (kL == 0)      || (0.5f * gl * gl >= thr);
    bool doneR = (kR == NB - 1) || (0.5f * gr * gr >= thr);

    int qslot = dir * TOTAL + b * NP + qt * 256 + tid;
    g_dist[qslot] = sqrtf(1e-6f + fmaxf(2.0f * thr, 0.0f));

    bool need = !(doneL && doneR);
    unsigned mask = __ballot_sync(FULLM, need);
    int nneed = __popc(mask);
    if (nneed) {
        int lane = tid & 31;
        int base = 0;
        if (lane == 0) base = atomicAdd(&g_nq, nneed);
        base = __shfl_sync(FULLM, base, 0);
        if (need) {
            int rank = __popc(mask & ((1u << lane) - 1));
            g_todo[base + rank] = make_int2(qslot, __float_as_int(m));
        }
    }
}

// Phase 2: one warp per unfinished query, exact range scan, warp fmin-reduce.
__global__ __launch_bounds__(256) void phase2_kernel() {
    int n = g_nq;
    int gw   = (blockIdx.x * 256 + threadIdx.x) >> 5;
    int lane = threadIdx.x & 31;
    const int nw = 256 * 8;               // 2048 warps

    for (int i = gw; i < n; i += nw) {
        int2 e = g_todo[i];
        int qslot = e.x;
        int dir = qslot >> 16;
        int rem = qslot & 65535;
        int b = rem >> 12, qi = rem & 4095;
        int qRow  = dir ? (16 + b) : b;
        int dbRow = dir ? b : (16 + b);
        const float4* db = g_sorted + (size_t)dbRow * NP;
        float4 q = g_sorted[(size_t)qRow * NP + qi];
        float m = __int_as_float(e.y);

        float d1 = sqrtf(fmaxf(2.0f * (q.w + m), 0.0f)) * 1.0005f + 1e-5f;
        int kLo = binof(q.x - d1);
        int kHi = binof(q.x + d1);
        int lo = g_binstart[dbRow][kLo];
        int hi = g_binstart[dbRow][kHi + 1];

        float mm = m;
        for (int j = lo + lane; j < hi; j += 32) {
            float4 p = __ldg(&db[j]);
            mm = fminf(mm, fmaf(-q.x, p.x, fmaf(-q.y, p.y, fmaf(-q.z, p.z, p.w))));
        }
        #pragma unroll
        for (int o = 16; o; o >>= 1)
            mm = fminf(mm, __shfl_xor_sync(FULLM, mm, o));
        if (lane == 0)
            g_dist[qslot] = sqrtf(1e-6f + fmaxf(2.0f * (q.w + mm), 0.0f));
    }
}

__global__ __launch_bounds__(256) void reduceA_kernel() {
    __shared__ float s[256];
    int blk = blockIdx.x, tid = threadIdx.x;
    float v = 0.0f;
    #pragma unroll
    for (int i = 0; i < 4; i++) v += g_dist[blk * 1024 + i * 256 + tid];
    s[tid] = v;
    __syncthreads();
    #pragma unroll
    for (int st = 128; st > 0; st >>= 1) {
        if (tid < st) s[tid] += s[tid + st];
        __syncthreads();
    }
    if (tid == 0) g_partA[blk] = s[0];
}

__global__ void reduceB_kernel(float* __restrict__ out) {
    __shared__ float s[128];
    int tid = threadIdx.x;
    s[tid] = g_partA[tid];
    __syncthreads();
    #pragma unroll
    for (int st = 64; st > 0; st >>= 1) {
        if (tid < st) s[tid] += s[tid + st];
        __syncthreads();
    }
    if (tid == 0) out[0] = s[0] * (1.0f / (float)TOTAL);
}

extern "C" void kernel_launch(void* const* d_in, const int* in_sizes, int n_in,
                              void* d_out, int out_size) {
    const float* x = (const float*)d_in[0];
    const float* y = (const float*)d_in[1];
    float* out = (float*)d_out;

    zero_kernel<<<ROWS, NB>>>();
    hist_kernel<<<256, 256>>>(x, y);
    prefix_kernel<<<ROWS, NB>>>();
    scatter_kernel<<<256, 256>>>(x, y);
    phase1_kernel<<<512, 256>>>();
    phase2_kernel<<<256, 256>>>();
    reduceA_kernel<<<128, 256>>>();
    reduceB_kernel<<<1, 128>>>(out);
}